// round 16
// baseline (speedup 1.0000x reference)
#include <cuda_runtime.h>
#include <cuda_bf16.h>
#include <math.h>
#include <stdint.h>

// Problem constants
#define B_  4
#define S_  256
#define V_  64
#define H_  128
#define NH_ 8
#define DH_ 16
#define LP1_ 11
#define NL_ 3
#define BT_ (B_ * S_)          // 1024
#define ZSZ (BT_ * V_ * H_)

// Scratch (device globals)
__device__ float g_adj[V_ * V_ * LP1_];
__device__ float g_zA[ZSZ];
__device__ float g_qb[ZSZ];
__device__ float g_kb[ZSZ];
__device__ float g_vb[ZSZ];
__device__ float g_ob[ZSZ];
// Pre-split weights: [pass 0..6][v][chunk 0..3][hi|lo] 10240-byte smem images
#define WIMG   10240
#define WVBLK  (4 * 2 * WIMG)    // 81920 bytes per (pass,v)
__device__ __align__(128) char g_Wc[7 * V_ * WVBLK];

extern __shared__ char SM[];

// ---------------------------------------------------------------------------
// mma.sync / ldmatrix helpers (validated R9-R15)
// ---------------------------------------------------------------------------
__device__ __forceinline__ uint32_t smem_u32(const void* p) {
    uint32_t a;
    asm("{ .reg .u64 t; cvta.to.shared.u64 t, %1; cvt.u32.u64 %0, t; }"
        : "=r"(a) : "l"(p));
    return a;
}
__device__ __forceinline__ void ldsm4(uint32_t& r0, uint32_t& r1,
                                      uint32_t& r2, uint32_t& r3, uint32_t addr) {
    asm volatile("ldmatrix.sync.aligned.m8n8.x4.shared.b16 {%0,%1,%2,%3}, [%4];"
                 : "=r"(r0), "=r"(r1), "=r"(r2), "=r"(r3) : "r"(addr));
}
__device__ __forceinline__ void mma16816(float* c, const uint32_t a[4],
                                         uint32_t b0, uint32_t b1) {
    asm volatile(
        "mma.sync.aligned.m16n8k16.row.col.f32.bf16.bf16.f32 "
        "{%0,%1,%2,%3}, {%4,%5,%6,%7}, {%8,%9}, {%0,%1,%2,%3};"
        : "+f"(c[0]), "+f"(c[1]), "+f"(c[2]), "+f"(c[3])
        : "r"(a[0]), "r"(a[1]), "r"(a[2]), "r"(a[3]), "r"(b0), "r"(b1));
}
__device__ __forceinline__ void split2(float x, float y,
                                       uint32_t& hi, uint32_t& lo) {
    __nv_bfloat162 h = __floats2bfloat162_rn(x, y);
    float rx = x - __bfloat162float(h.x);
    float ry = y - __bfloat162float(h.y);
    __nv_bfloat162 l = __floats2bfloat162_rn(rx, ry);
    hi = *(uint32_t*)&h;
    lo = *(uint32_t*)&l;
}

// ---------------------------------------------------------------------------
// Kernel 0: adj = sigmoid(adjacency_logits)
// ---------------------------------------------------------------------------
__global__ void sigmoid_kernel(const float* __restrict__ logits) {
    int i = blockIdx.x * 256 + threadIdx.x;
    if (i < V_ * V_ * LP1_) g_adj[i] = 1.0f / (1.0f + __expf(-logits[i]));
}

// ---------------------------------------------------------------------------
// Kernel P: split weights into per-chunk bf16 hi/lo smem images.
// ---------------------------------------------------------------------------
#define PREP_SMEM (128 * 132 * 4)
__global__ void prep_w_kernel(const float* __restrict__ mech_W,
                              const float* __restrict__ Wq,
                              const float* __restrict__ Wk,
                              const float* __restrict__ Wv,
                              const float* __restrict__ Wo) {
    float* Wt = (float*)SM;
    int pv = blockIdx.x;
    int pass = pv >> 6, v = pv & 63;
    const float* src;
    if (pass < 3)       src = mech_W + ((size_t)v * NL_ + pass) * H_ * H_;
    else if (pass == 3) src = Wq + (size_t)v * H_ * H_;
    else if (pass == 4) src = Wk + (size_t)v * H_ * H_;
    else if (pass == 5) src = Wv + (size_t)v * H_ * H_;
    else                src = Wo + (size_t)v * H_ * H_;

    int tid = threadIdx.x;
    for (int i = tid; i < 128 * 32; i += 256) {
        int r = i >> 5, c4 = i & 31;
        float4 a = *(const float4*)(src + (size_t)r * H_ + c4 * 4);
        *(float4*)(Wt + r * 132 + c4 * 4) = a;
    }
    __syncthreads();

    char* img = g_Wc + (size_t)pv * WVBLK;
    for (int task = tid; task < 4 * 128 * 16; task += 256) {
        int ch = task >> 11;
        int rem = task & 2047;
        int n = rem >> 4, kk2 = rem & 15;
        int k = ch * 32 + kk2 * 2;
        float w0 = Wt[k * 132 + n];
        float w1 = Wt[(k + 1) * 132 + n];
        uint32_t hi, lo;
        split2(w0, w1, hi, lo);
        *(uint32_t*)(img + (ch * 2 + 0) * WIMG + n * 80 + kk2 * 4) = hi;
        *(uint32_t*)(img + (ch * 2 + 1) * WIMG + n * 80 + kk2 * 4) = lo;
    }
}

// ---------------------------------------------------------------------------
// Kernel 1: causal input (R6 proven)
// ---------------------------------------------------------------------------
#define CAU_XW   0
#define CAU_ASM  (CAU_XW + LP1_ * 64)
#define CAU_BL   (CAU_ASM + 64 * 65)
#define CAU_VE   (CAU_BL + 64 * 12)
#define CAU_TE   (CAU_VE + 64 * 128)
#define CAU_SMEM ((CAU_TE + LP1_ * 128) * 4)

__global__ void causal_kernel(const float* __restrict__ x,
                              const float* __restrict__ var_emb,
                              const float* __restrict__ temp_emb,
                              float* __restrict__ zout) {
    float* cs = (float*)SM;
    float* xw  = cs + CAU_XW;
    float* Asm = cs + CAU_ASM;
    float* Bl  = cs + CAU_BL;
    float* ve  = cs + CAU_VE;
    float* te  = cs + CAU_TE;

    int bt = blockIdx.x;
    int b = bt / S_;
    int t = bt % S_;
    int tid = threadIdx.x;

    for (int e = tid; e < LP1_ * 64; e += 256) {
        int l = e >> 6, s2 = e & 63;
        int tt = t - l;
        xw[l * 64 + s2] = (tt >= 0) ? x[(b * S_ + tt) * V_ + s2] : 0.0f;
    }
    for (int e = tid; e < 64 * 128 / 4; e += 256)
        ((float4*)ve)[e] = ((const float4*)var_emb)[e];
    for (int e = tid; e < LP1_ * 128 / 4; e += 256)
        ((float4*)te)[e] = ((const float4*)temp_emb)[e];
    __syncthreads();

    for (int e = tid; e < 64 * 64; e += 256) {
        int i = e >> 6, s2 = e & 63;
        const float* ap = g_adj + (s2 * V_ + i) * LP1_;
        float acc = 0.0f;
#pragma unroll
        for (int l = 0; l < LP1_; l++) acc += xw[l * 64 + s2] * ap[l];
        Asm[i * 65 + s2] = acc;
    }
    for (int e = tid; e < 64 * LP1_; e += 256) {
        int i = e / LP1_, l = e % LP1_;
        float acc = 0.0f;
        for (int s2 = 0; s2 < 64; s2++)
            acc += xw[l * 64 + s2] * g_adj[(s2 * V_ + i) * LP1_ + l];
        Bl[i * 12 + l] = acc;
    }
    __syncthreads();

    int i = tid >> 2, q = tid & 3;
    float4 acc[8];
#pragma unroll
    for (int j = 0; j < 8; j++) acc[j] = make_float4(0.f, 0.f, 0.f, 0.f);

    for (int s2 = 0; s2 < 64; s2++) {
        float a = Asm[i * 65 + s2];
        const float* vr = ve + s2 * 128 + q * 4;
#pragma unroll
        for (int j = 0; j < 8; j++) {
            float4 vv = *(const float4*)(vr + j * 16);
            acc[j].x += a * vv.x; acc[j].y += a * vv.y;
            acc[j].z += a * vv.z; acc[j].w += a * vv.w;
        }
    }
#pragma unroll
    for (int l = 0; l < LP1_; l++) {
        float bl = Bl[i * 12 + l];
        const float* tr = te + l * 128 + q * 4;
#pragma unroll
        for (int j = 0; j < 8; j++) {
            float4 vv = *(const float4*)(tr + j * 16);
            acc[j].x += bl * vv.x; acc[j].y += bl * vv.y;
            acc[j].z += bl * vv.z; acc[j].w += bl * vv.w;
        }
    }
    float* zr = zout + ((size_t)i * BT_ + bt) * H_ + q * 4;
#pragma unroll
    for (int j = 0; j < 8; j++) *(float4*)(zr + j * 16) = acc[j];
}

// ---------------------------------------------------------------------------
// Kernel 2: MEGA mma v3 (R15 proven) — 512 threads, W register-prefetch.
// ---------------------------------------------------------------------------
#define GAP 80
#define MZ_HI 0
#define MZ_LO 40960
#define MW_HI 81920
#define MW_LO 92160
#define MEGA_SMEM 102400

__global__ __launch_bounds__(512, 2) void mega_mma(
    const float* __restrict__ zin,
    const float* __restrict__ mech_b,
    const float* __restrict__ ln_g, const float* __restrict__ ln_b,
    const float* __restrict__ bq, const float* __restrict__ bk,
    const float* __restrict__ bv,
    float* __restrict__ qb, float* __restrict__ kb, float* __restrict__ vb) {
    char* smc = SM;
    uint32_t sb = smem_u32(smc);
    int tid = threadIdx.x;
    int v = blockIdx.y;
    int bt0 = blockIdx.x * 128;

    int wid = tid >> 5, lane = tid & 31;
    int ch2 = wid >> 3;
    int rg  = wid & 7;
    int g = lane >> 2, tg = lane & 3;
    int lr = lane & 7, lsel = (lane >> 3) & 1, khalf = lane >> 4;
    uint32_t aoff = (uint32_t)(rg * 16 + lr + lsel * 8) * GAP + khalf * 16;
    int r0 = rg * 16 + g;

    const uint4* wimg0 = (const uint4*)(g_Wc + (size_t)(0 * V_ + v) * WVBLK);
    uint4 wpre[3];

    const float* inp = zin + ((size_t)v * BT_ + bt0) * H_;
#pragma unroll
    for (int t = 0; t < 8; t++) {
        int idx = tid + t * 512;
        int r = idx >> 5, c4 = idx & 31;
        float4 a = *(const float4*)(inp + (size_t)r * H_ + c4 * 4);
        uint32_t h0, l0, h1, l1;
        split2(a.x, a.y, h0, l0);
        split2(a.z, a.w, h1, l1);
        uint32_t off = (uint32_t)(c4 >> 3) * WIMG + r * GAP + (c4 & 7) * 8;
        *(uint2*)(smc + MZ_HI + off) = make_uint2(h0, h1);
        *(uint2*)(smc + MZ_LO + off) = make_uint2(l0, l1);
    }
    wpre[0] = wimg0[tid];
    wpre[1] = wimg0[tid + 512];
    if (tid < 256) wpre[2] = wimg0[tid + 1024];
    __syncthreads();

    for (int layer = 0; layer < 6; layer++) {
        float c[8][4];
#pragma unroll
        for (int nt = 0; nt < 8; nt++)
#pragma unroll
            for (int e = 0; e < 4; e++) c[nt][e] = 0.0f;

        for (int ch = 0; ch < 4; ch++) {
            uint4* dst = (uint4*)(smc + MW_HI);
            dst[tid] = wpre[0];
            dst[tid + 512] = wpre[1];
            if (tid < 256) dst[tid + 1024] = wpre[2];
            __syncthreads();

            {
                const uint4* nsrc;
                if (ch < 3) {
                    nsrc = (const uint4*)(g_Wc + (size_t)(layer * V_ + v) * WVBLK)
                         + (ch + 1) * 1280;
                } else if (layer < 5) {
                    nsrc = (const uint4*)(g_Wc + (size_t)((layer + 1) * V_ + v) * WVBLK);
                } else {
                    nsrc = nullptr;
                }
                if (nsrc) {
                    wpre[0] = nsrc[tid];
                    wpre[1] = nsrc[tid + 512];
                    if (tid < 256) wpre[2] = nsrc[tid + 1024];
                }
            }

            uint32_t azh = sb + MZ_HI + ch * WIMG;
            uint32_t azl = sb + MZ_LO + ch * WIMG;
#pragma unroll
            for (int sub = 0; sub < 2; sub++) {
                uint32_t ah[4], al[4];
                ldsm4(ah[0], ah[1], ah[2], ah[3], azh + aoff + sub * 32);
                ldsm4(al[0], al[1], al[2], al[3], azl + aoff + sub * 32);
#pragma unroll
                for (int bq8 = 0; bq8 < 4; bq8++) {
                    uint32_t bo = (uint32_t)(ch2 * 64 + bq8 * 16 + lr + khalf * 8) * GAP
                                + lsel * 16 + sub * 32;
                    uint32_t bh[4], bl[4];
                    ldsm4(bh[0], bh[1], bh[2], bh[3], sb + MW_HI + bo);
                    ldsm4(bl[0], bl[1], bl[2], bl[3], sb + MW_LO + bo);
                    mma16816(c[2 * bq8 + 0], ah, bh[0], bh[1]);
                    mma16816(c[2 * bq8 + 1], ah, bh[2], bh[3]);
                    mma16816(c[2 * bq8 + 0], ah, bl[0], bl[1]);
                    mma16816(c[2 * bq8 + 1], ah, bl[2], bl[3]);
                    mma16816(c[2 * bq8 + 0], al, bh[0], bh[1]);
                    mma16816(c[2 * bq8 + 1], al, bh[2], bh[3]);
                }
            }
            __syncthreads();
        }

        if (layer < 3) {
            const float* bias = mech_b + ((size_t)v * NL_ + layer) * H_ + ch2 * 64;
            const float* gg = ln_g + ((size_t)v * NL_ + layer) * H_ + ch2 * 64;
            const float* nb = ln_b + ((size_t)v * NL_ + layer) * H_ + ch2 * 64;

            float sA = 0.0f, sB = 0.0f, qA = 0.0f, qB = 0.0f;
#pragma unroll
            for (int nt = 0; nt < 8; nt++) {
                float2 b2 = __ldg((const float2*)(bias + nt * 8 + 2 * tg));
                c[nt][0] += b2.x; c[nt][1] += b2.y;
                c[nt][2] += b2.x; c[nt][3] += b2.y;
                sA += c[nt][0] + c[nt][1];
                sB += c[nt][2] + c[nt][3];
                qA += c[nt][0] * c[nt][0] + c[nt][1] * c[nt][1];
                qB += c[nt][2] * c[nt][2] + c[nt][3] * c[nt][3];
            }
            sA += __shfl_xor_sync(~0u, sA, 1); sA += __shfl_xor_sync(~0u, sA, 2);
            sB += __shfl_xor_sync(~0u, sB, 1); sB += __shfl_xor_sync(~0u, sB, 2);
            qA += __shfl_xor_sync(~0u, qA, 1); qA += __shfl_xor_sync(~0u, qA, 2);
            qB += __shfl_xor_sync(~0u, qB, 1); qB += __shfl_xor_sync(~0u, qB, 2);

            float2* red = (float2*)(smc + MW_HI);
            if (tg == 0) {
                red[ch2 * 128 + r0] = make_float2(sA, qA);
                red[ch2 * 128 + r0 + 8] = make_float2(sB, qB);
            }
            __syncthreads();
            float2 oA = red[(1 - ch2) * 128 + r0];
            float2 oB = red[(1 - ch2) * 128 + r0 + 8];
            float muA = (sA + oA.x) * (1.0f / H_);
            float muB = (sB + oB.x) * (1.0f / H_);
            float vA = (qA + oA.y) * (1.0f / H_) - muA * muA;
            float vB = (qB + oB.y) * (1.0f / H_) - muB * muB;
            float ivA = rsqrtf(vA + 1e-5f);
            float ivB = rsqrtf(vB + 1e-5f);

#pragma unroll
            for (int nt = 0; nt < 8; nt++) {
                float2 g2 = __ldg((const float2*)(gg + nt * 8 + 2 * tg));
                float2 n2 = __ldg((const float2*)(nb + nt * 8 + 2 * tg));
                float y0 = (c[nt][0] - muA) * ivA * g2.x + n2.x;
                float y1 = (c[nt][1] - muA) * ivA * g2.y + n2.y;
                float y2 = (c[nt][2] - muB) * ivB * g2.x + n2.x;
                float y3 = (c[nt][3] - muB) * ivB * g2.y + n2.y;
                y0 = y0 * 0.5f * (1.0f + erff(y0 * 0.70710678118654752f));
                y1 = y1 * 0.5f * (1.0f + erff(y1 * 0.70710678118654752f));
                y2 = y2 * 0.5f * (1.0f + erff(y2 * 0.70710678118654752f));
                y3 = y3 * 0.5f * (1.0f + erff(y3 * 0.70710678118654752f));
                uint32_t hiA, loA, hiB, loB;
                split2(y0, y1, hiA, loA);
                split2(y2, y3, hiB, loB);
                int ntp = ch2 * 8 + nt;
                uint32_t addr = (uint32_t)(ntp >> 2) * WIMG + r0 * GAP
                              + ((ntp & 3) * 4 + tg) * 4;
                *(uint32_t*)(smc + MZ_HI + addr) = hiA;
                *(uint32_t*)(smc + MZ_LO + addr) = loA;
                *(uint32_t*)(smc + MZ_HI + addr + 8 * GAP) = hiB;
                *(uint32_t*)(smc + MZ_LO + addr + 8 * GAP) = loB;
            }
            __syncthreads();
        } else {
            const float* bias = (layer == 3 ? bq : layer == 4 ? bk : bv)
                              + (size_t)v * H_ + ch2 * 64;
            float* out = (layer == 3 ? qb : layer == 4 ? kb : vb);
            float* ob0 = out + ((size_t)v * BT_ + bt0 + r0) * H_ + ch2 * 64;
            float* ob1 = ob0 + 8 * H_;
#pragma unroll
            for (int nt = 0; nt < 8; nt++) {
                float2 b2 = __ldg((const float2*)(bias + nt * 8 + 2 * tg));
                *(float2*)(ob0 + nt * 8 + 2 * tg) =
                    make_float2(c[nt][0] + b2.x, c[nt][1] + b2.y);
                *(float2*)(ob1 + nt * 8 + 2 * tg) =
                    make_float2(c[nt][2] + b2.x, c[nt][3] + b2.y);
            }
        }
    }
}

// ---------------------------------------------------------------------------
// Kernel 2b: Wo GEMM + fused output head (R11/R13 proven, unchanged)
// ---------------------------------------------------------------------------
#define GB_HI 20480
#define GB_LO 30720
#define G2_SMEM 40960

__global__ __launch_bounds__(256, 2) void wo_head_mma(
    const float* __restrict__ in,
    const float* __restrict__ bo,
    const float* __restrict__ OW, const float* __restrict__ OB,
    float* __restrict__ PRED) {
    char* smc = SM;
    uint32_t sb = smem_u32(smc);
    int tid = threadIdx.x;
    int v = blockIdx.y;
    int bt0 = blockIdx.x * 128;

    const float* bias = bo + (size_t)v * H_;
    const float* inp = in + ((size_t)v * BT_ + bt0) * H_;
    const uint4* wimg = (const uint4*)(g_Wc + (size_t)(6 * V_ + v) * WVBLK);

    int wid = tid >> 5, lane = tid & 31;
    int g = lane >> 2, tg = lane & 3;
    int lr = lane & 7, lsel = (lane >> 3) & 1, khalf = lane >> 4;
    uint32_t aoff = (uint32_t)(wid * 16 + lr + lsel * 8) * GAP + khalf * 16;

    float c[16][4];
#pragma unroll
    for (int nt = 0; nt < 16; nt++)
#pragma unroll
        for (int e = 0; e < 4; e++) c[nt][e] = 0.0f;

    for (int ch = 0; ch < 4; ch++) {
#pragma unroll
        for (int t = 0; t < 4; t++) {
            int idx = tid + t * 256;
            int r = idx >> 3, c4 = idx & 7;
            float4 a = *(const float4*)(inp + (size_t)r * H_ + ch * 32 + c4 * 4);
            uint32_t h0, l0, h1, l1;
            split2(a.x, a.y, h0, l0);
            split2(a.z, a.w, h1, l1);
            *(uint2*)(smc + r * GAP + c4 * 8) = make_uint2(h0, h1);
            *(uint2*)(smc + 10240 + r * GAP + c4 * 8) = make_uint2(l0, l1);
        }
        {
            const uint4* src = wimg + ch * 1280;
            uint4* dst = (uint4*)(smc + GB_HI);
            for (int i = tid; i < 1280; i += 256) dst[i] = src[i];
        }
        __syncthreads();

#pragma unroll
        for (int sub = 0; sub < 2; sub++) {
            uint32_t ah[4], al[4];
            ldsm4(ah[0], ah[1], ah[2], ah[3], sb + aoff + sub * 32);
            ldsm4(al[0], al[1], al[2], al[3], sb + 10240 + aoff + sub * 32);
#pragma unroll
            for (int bq8 = 0; bq8 < 8; bq8++) {
                uint32_t bo2 = (uint32_t)(bq8 * 16 + lr + khalf * 8) * GAP
                             + lsel * 16 + sub * 32;
                uint32_t bh[4], bl[4];
                ldsm4(bh[0], bh[1], bh[2], bh[3], sb + GB_HI + bo2);
                ldsm4(bl[0], bl[1], bl[2], bl[3], sb + GB_LO + bo2);
                mma16816(c[2 * bq8 + 0], ah, bh[0], bh[1]);
                mma16816(c[2 * bq8 + 1], ah, bh[2], bh[3]);
                mma16816(c[2 * bq8 + 0], ah, bl[0], bl[1]);
                mma16816(c[2 * bq8 + 1], ah, bl[2], bl[3]);
                mma16816(c[2 * bq8 + 0], al, bh[0], bh[1]);
                mma16816(c[2 * bq8 + 1], al, bh[2], bh[3]);
            }
        }
        __syncthreads();
    }

    int r0 = bt0 + wid * 16 + g;
    const float* ow = OW + (size_t)v * H_;
    float s0 = 0.0f, s1 = 0.0f;
#pragma unroll
    for (int nt = 0; nt < 16; nt++) {
        float2 b2 = __ldg((const float2*)(bias + nt * 8 + 2 * tg));
        float2 w2 = __ldg((const float2*)(ow + nt * 8 + 2 * tg));
        s0 += (c[nt][0] + b2.x) * w2.x + (c[nt][1] + b2.y) * w2.y;
        s1 += (c[nt][2] + b2.x) * w2.x + (c[nt][3] + b2.y) * w2.y;
    }
    s0 += __shfl_xor_sync(~0u, s0, 1); s0 += __shfl_xor_sync(~0u, s0, 2);
    s1 += __shfl_xor_sync(~0u, s1, 1); s1 += __shfl_xor_sync(~0u, s1, 2);
    if (tg == 0) {
        float obv = OB[v];
        PRED[(size_t)r0 * V_ + v] = s0 + obv;
        PRED[(size_t)(r0 + 8) * V_ + v] = s1 + obv;
    }
}

// ---------------------------------------------------------------------------
// Kernel 3: tensor-core attention v3 — block = single (b,v,head).
// smem 41472 B (half of v2) -> occ 3 via launch_bounds(256,3).
// Warp = 32 q rows (2 strips of 16). Online softmax + dual P.V accumulators.
// ---------------------------------------------------------------------------
#define AKHI 0
#define AKLO 12288
#define AVHI 24576
#define AVLO 33024
#define ATT_SMEM 41472

__global__ __launch_bounds__(256, 3) void attn_mma(
        const float* __restrict__ qg,
        const float* __restrict__ kg,
        const float* __restrict__ vg,
        float* __restrict__ og) {
    char* smc = SM;
    uint32_t sb = smem_u32(smc);
    int id = blockIdx.x;
    int hd = id & 7;                  // head
    int vv = (id >> 3) & 63;
    int b  = id >> 9;
    int tid = threadIdx.x;

    size_t vbase = ((size_t)vv * BT_ + b * S_) * H_;

    // stage K (row-major, pitch 48) and V^T (pitch 528) as bf16 hi/lo
    for (int i = tid; i < 4096; i += 256) {
        int key = i >> 4, d = i & 15;
        size_t gidx = vbase + (size_t)key * H_ + hd * 16 + d;
        float kv = kg[gidx];
        __nv_bfloat16 kh = __float2bfloat16(kv);
        __nv_bfloat16 kl = __float2bfloat16(kv - __bfloat162float(kh));
        *(__nv_bfloat16*)(smc + AKHI + key * 48 + d * 2) = kh;
        *(__nv_bfloat16*)(smc + AKLO + key * 48 + d * 2) = kl;
        float vvv = vg[gidx];
        __nv_bfloat16 vh = __float2bfloat16(vvv);
        __nv_bfloat16 vl = __float2bfloat16(vvv - __bfloat162float(vh));
        *(__nv_bfloat16*)(smc + AVHI + d * 528 + key * 2) = vh;
        *(__nv_bfloat16*)(smc + AVLO + d * 528 + key * 2) = vl;
    }
    __syncthreads();

    int wid = tid >> 5, lane = tid & 31;
    int g = lane >> 2, tg = lane & 3;
    int lr = lane & 7, lsel = (lane >> 3) & 1, khalf = lane >> 4;

    const float* qbase = qg + vbase + hd * 16;
    float* obase = og + vbase + hd * 16;

    uint32_t kbh = sb + AKHI;
    uint32_t kbl = sb + AKLO;
    uint32_t vbh = sb + AVHI;
    uint32_t vbl = sb + AVLO;
    uint32_t krow = (uint32_t)(lr + khalf * 8) * 48 + lsel * 16;
    uint32_t vrow = (uint32_t)(lr + khalf * 8) * 528 + lsel * 16;

    for (int s = 0; s < 2; s++) {
        int q0 = wid * 32 + s * 16;

        uint32_t ah[4], al[4];
        {
            float2 f0 = *(const float2*)(qbase + (size_t)(q0 + g) * H_ + 2 * tg);
            float2 f1 = *(const float2*)(qbase + (size_t)(q0 + g + 8) * H_ + 2 * tg);
            float2 f2 = *(const float2*)(qbase + (size_t)(q0 + g) * H_ + 8 + 2 * tg);
            float2 f3 = *(const float2*)(qbase + (size_t)(q0 + g + 8) * H_ + 8 + 2 * tg);
            split2(f0.x, f0.y, ah[0], al[0]);
            split2(f1.x, f1.y, ah[1], al[1]);
            split2(f2.x, f2.y, ah[2], al[2]);
            split2(f3.x, f3.y, ah[3], al[3]);
        }

        float o[8], o2[8];
#pragma unroll
        for (int e = 0; e < 8; e++) { o[e] = 0.0f; o2[e] = 0.0f; }
        float mA = -1e30f, mB = -1e30f, sA = 0.0f, sB = 0.0f;

        for (int kc = 0; kc < 4; kc++) {
            float cc[4][8];
#pragma unroll
            for (int kt = 0; kt < 4; kt++)
#pragma unroll
                for (int e = 0; e < 8; e++) cc[kt][e] = 0.0f;

#pragma unroll
            for (int kt = 0; kt < 4; kt++) {
                int kta = kc * 4 + kt;
                uint32_t bh[4], bl[4];
                ldsm4(bh[0], bh[1], bh[2], bh[3], kbh + kta * 768 + krow);
                ldsm4(bl[0], bl[1], bl[2], bl[3], kbl + kta * 768 + krow);
                mma16816(cc[kt], ah, bh[0], bh[1]);
                mma16816(cc[kt] + 4, ah, bh[2], bh[3]);
                mma16816(cc[kt], ah, bl[0], bl[1]);
                mma16816(cc[kt] + 4, ah, bl[2], bl[3]);
                mma16816(cc[kt], al, bh[0], bh[1]);
                mma16816(cc[kt] + 4, al, bh[2], bh[3]);
            }

            float cmA = -1e30f, cmB = -1e30f;
#pragma unroll
            for (int kt = 0; kt < 4; kt++)
#pragma unroll
                for (int t = 0; t < 2; t++) {
                    cmA = fmaxf(cmA, fmaxf(cc[kt][t * 4 + 0], cc[kt][t * 4 + 1]));
                    cmB = fmaxf(cmB, fmaxf(cc[kt][t * 4 + 2], cc[kt][t * 4 + 3]));
                }
            cmA = fmaxf(cmA, __shfl_xor_sync(~0u, cmA, 1));
            cmA = fmaxf(cmA, __shfl_xor_sync(~0u, cmA, 2));
            cmB = fmaxf(cmB, __shfl_xor_sync(~0u, cmB, 1));
            cmB = fmaxf(cmB, __shfl_xor_sync(~0u, cmB, 2));
            cmA *= 0.25f; cmB *= 0.25f;
            float mnA = fmaxf(mA, cmA), mnB = fmaxf(mB, cmB);
            float fA = __expf(mA - mnA), fB = __expf(mB - mnB);
            mA = mnA; mB = mnB;
            sA *= fA; sB *= fB;
#pragma unroll
            for (int t = 0; t < 2; t++) {
                o[t * 4 + 0] *= fA;  o[t * 4 + 1] *= fA;
                o[t * 4 + 2] *= fB;  o[t * 4 + 3] *= fB;
                o2[t * 4 + 0] *= fA; o2[t * 4 + 1] *= fA;
                o2[t * 4 + 2] *= fB; o2[t * 4 + 3] *= fB;
            }

#pragma unroll
            for (int kt = 0; kt < 4; kt++) {
                int kta = kc * 4 + kt;
                float* ot = (kt & 1) ? o2 : o;
                float p[8];
#pragma unroll
                for (int t = 0; t < 2; t++) {
                    p[t * 4 + 0] = __expf(cc[kt][t * 4 + 0] * 0.25f - mA);
                    p[t * 4 + 1] = __expf(cc[kt][t * 4 + 1] * 0.25f - mA);
                    p[t * 4 + 2] = __expf(cc[kt][t * 4 + 2] * 0.25f - mB);
                    p[t * 4 + 3] = __expf(cc[kt][t * 4 + 3] * 0.25f - mB);
                    sA += p[t * 4 + 0] + p[t * 4 + 1];
                    sB += p[t * 4 + 2] + p[t * 4 + 3];
                }
                uint32_t ph[4], pl[4];
                split2(p[0], p[1], ph[0], pl[0]);
                split2(p[2], p[3], ph[1], pl[1]);
                split2(p[4], p[5], ph[2], pl[2]);
                split2(p[6], p[7], ph[3], pl[3]);
                uint32_t vh[4], vl[4];
                ldsm4(vh[0], vh[1], vh[2], vh[3], vbh + vrow + kta * 32);
                ldsm4(vl[0], vl[1], vl[2], vl[3], vbl + vrow + kta * 32);
                mma16816(ot, ph, vh[0], vh[1]);
                mma16816(ot + 4, ph, vh[2], vh[3]);
                mma16816(ot, ph, vl[0], vl[1]);
                mma16816(ot + 4, ph, vl[2], vl[3]);
                mma16816(ot, pl, vh[0], vh[1]);
                mma16816(ot + 4, pl, vh[2], vh[3]);
            }
        }

        sA += __shfl_xor_sync(~0u, sA, 1);
        sA += __shfl_xor_sync(~0u, sA, 2);
        sB += __shfl_xor_sync(~0u, sB, 1);
        sB += __shfl_xor_sync(~0u, sB, 2);
        float invA = 1.0f / sA, invB = 1.0f / sB;
#pragma unroll
        for (int e = 0; e < 8; e++) o[e] += o2[e];

        *(float2*)(obase + (size_t)(q0 + g) * H_ + 2 * tg) =
            make_float2(o[0] * invA, o[1] * invA);
        *(float2*)(obase + (size_t)(q0 + g + 8) * H_ + 2 * tg) =
            make_float2(o[2] * invB, o[3] * invB);
        *(float2*)(obase + (size_t)(q0 + g) * H_ + 8 + 2 * tg) =
            make_float2(o[4] * invA, o[5] * invA);
        *(float2*)(obase + (size_t)(q0 + g + 8) * H_ + 8 + 2 * tg) =
            make_float2(o[6] * invB, o[7] * invB);
    }
}

// ---------------------------------------------------------------------------
// Launch
// ---------------------------------------------------------------------------
extern "C" void kernel_launch(void* const* d_in, const int* in_sizes, int n_in,
                              void* d_out, int out_size) {
    const float* x       = (const float*)d_in[0];
    const float* adj_l   = (const float*)d_in[1];
    const float* var_emb = (const float*)d_in[2];
    const float* temp_emb= (const float*)d_in[3];
    const float* mech_W  = (const float*)d_in[4];
    const float* mech_b  = (const float*)d_in[5];
    const float* ln_g    = (const float*)d_in[6];
    const float* ln_b    = (const float*)d_in[7];
    const float* Wq      = (const float*)d_in[8];
    const float* Wk      = (const float*)d_in[9];
    const float* Wv      = (const float*)d_in[10];
    const float* Wo      = (const float*)d_in[11];
    const float* bq      = (const float*)d_in[12];
    const float* bk      = (const float*)d_in[13];
    const float* bv      = (const float*)d_in[14];
    const float* bo      = (const float*)d_in[15];
    const float* out_W   = (const float*)d_in[16];
    const float* out_b   = (const float*)d_in[17];
    float* pred = (float*)d_out;

    float *zA, *qb, *kb, *vb, *ob;
    cudaGetSymbolAddress((void**)&zA, g_zA);
    cudaGetSymbolAddress((void**)&qb, g_qb);
    cudaGetSymbolAddress((void**)&kb, g_kb);
    cudaGetSymbolAddress((void**)&vb, g_vb);
    cudaGetSymbolAddress((void**)&ob, g_ob);

    cudaFuncSetAttribute((const void*)mega_mma,
                         cudaFuncAttributeMaxDynamicSharedMemorySize, MEGA_SMEM);
    cudaFuncSetAttribute((const void*)wo_head_mma,
                         cudaFuncAttributeMaxDynamicSharedMemorySize, G2_SMEM);
    cudaFuncSetAttribute((const void*)prep_w_kernel,
                         cudaFuncAttributeMaxDynamicSharedMemorySize, PREP_SMEM);
    cudaFuncSetAttribute((const void*)causal_kernel,
                         cudaFuncAttributeMaxDynamicSharedMemorySize, CAU_SMEM);
    cudaFuncSetAttribute((const void*)attn_mma,
                         cudaFuncAttributeMaxDynamicSharedMemorySize, ATT_SMEM);

    // 0. sigmoid + weight split
    sigmoid_kernel<<<(V_ * V_ * LP1_ + 255) / 256, 256>>>(adj_l);
    prep_w_kernel<<<7 * V_, 256, PREP_SMEM>>>(mech_W, Wq, Wk, Wv, Wo);

    // 1. causal input -> zA  ([v][bt][h])
    causal_kernel<<<BT_, 256, CAU_SMEM>>>(x, var_emb, temp_emb, zA);

    // 2. MEGA: mech0..2 + Q/K/V, activations resident in smem (512 threads)
    dim3 mgrid(BT_ / 128, V_);
    mega_mma<<<mgrid, 512, MEGA_SMEM>>>(zA, mech_b, ln_g, ln_b,
                                        bq, bk, bv, qb, kb, vb);

    // 3. tensor-core attention (single-head blocks, occ 3) -> ob
    attn_mma<<<B_ * V_ * NH_, 256, ATT_SMEM>>>(qb, kb, vb, ob);

    // 4. Wo + fused output head -> pred
    wo_head_mma<<<mgrid, 256, G2_SMEM>>>(ob, bo, out_W, out_b, pred);
}